// round 14
// baseline (speedup 1.0000x reference)
#include <cuda_runtime.h>
#include <cuda_fp16.h>
#include <cstdint>

// ---------------- problem constants ----------------
#define BQ 64            // batch (GEMM M)
#define MB 256           // bank entries (GEMM N)
#define DLL 524288LL     // feature dim K
#define KT 32            // K per tile
#define NTT 16384        // DLL / KT
#define NCTA2 304        // 2 CTAs per SM
#define SDIM 2048        // style dim
#define NGRP 16          // reduction groups
#define CPG  (NCTA2 / NGRP)   // 19 chunks per group

// static scratch
__device__ float g_psim[NCTA2 * BQ * MB];     // [chunk][b][m]
__device__ float g_pnorm[NCTA2 * MB];         // [chunk][m]
__device__ float g_part[BQ * NGRP * MB];      // [b][g][m]
__device__ float g_npart[NGRP * MB];          // [g][m]

// ---------------- smem layout (bytes, per buffer) ----------------
// A (content): [64 b][64 B row, XOR-swizzled 16B chunks]  (hi, lo) = 4 KB each
// B (bank)   : [32 k][n pitch 264] fp16 = 16896 B (hi only)  -- R11 layout
#define A_HI 0u
#define A_LO 4096u
#define B_HI 8192u
#define BUFB 25088u
#define SMEM_TOTAL (2u * BUFB)   // 50176 per CTA; x2 CTAs ~ 100 KB/SM

// ---------------- helpers ----------------
static __device__ __forceinline__ uint32_t smem_u32(const void* p) {
    uint32_t a;
    asm("{ .reg .u64 t; cvta.to.shared.u64 t, %1; cvt.u32.u64 %0, t; }"
        : "=r"(a) : "l"(p));
    return a;
}
static __device__ __forceinline__ void ldsm4(uint32_t* r, uint32_t addr) {
    asm volatile("ldmatrix.sync.aligned.m8n8.x4.shared.b16 {%0,%1,%2,%3}, [%4];"
                 : "=r"(r[0]), "=r"(r[1]), "=r"(r[2]), "=r"(r[3]) : "r"(addr));
}
static __device__ __forceinline__ void ldsm4t(uint32_t* r, uint32_t addr) {
    asm volatile("ldmatrix.sync.aligned.m8n8.x4.trans.shared.b16 {%0,%1,%2,%3}, [%4];"
                 : "=r"(r[0]), "=r"(r[1]), "=r"(r[2]), "=r"(r[3]) : "r"(addr));
}
static __device__ __forceinline__ void mma16816(float* c, const uint32_t* a,
                                                const uint32_t* b) {
    asm volatile(
        "mma.sync.aligned.m16n8k16.row.col.f32.f16.f16.f32 "
        "{%0,%1,%2,%3}, {%4,%5,%6,%7}, {%8,%9}, {%0,%1,%2,%3};"
        : "+f"(c[0]), "+f"(c[1]), "+f"(c[2]), "+f"(c[3])
        : "r"(a[0]), "r"(a[1]), "r"(a[2]), "r"(a[3]), "r"(b[0]), "r"(b[1]));
}
// fp32x4 -> fp16 hi/lo pairs (A side)
static __device__ __forceinline__ void cvt4h(float4 v, uint2& hi, uint2& lo) {
    __half2 h0 = __floats2half2_rn(v.x, v.y);
    __half2 h1 = __floats2half2_rn(v.z, v.w);
    float2 f0 = __half22float2(h0);
    float2 f1 = __half22float2(h1);
    __half2 l0 = __floats2half2_rn(v.x - f0.x, v.y - f0.y);
    __half2 l1 = __floats2half2_rn(v.z - f1.x, v.w - f1.y);
    hi = make_uint2(*(uint32_t*)&h0, *(uint32_t*)&h1);
    lo = make_uint2(*(uint32_t*)&l0, *(uint32_t*)&l1);
}
// fp32x4 -> fp16x4 (B side, single term)
static __device__ __forceinline__ uint2 cvt4s(float4 v) {
    __half2 h0 = __floats2half2_rn(v.x, v.y);
    __half2 h1 = __floats2half2_rn(v.z, v.w);
    return make_uint2(*(uint32_t*)&h0, *(uint32_t*)&h1);
}
// XOR-swizzled A STS offset (verified R5/R12): f in [0,512)
static __device__ __forceinline__ uint32_t a_sts(int f) {
    const uint32_t b = (uint32_t)f >> 3, k4 = (uint32_t)f & 7u;
    return b * 64u + (((k4 >> 1) ^ ((b >> 1) & 3u)) << 4) + ((k4 & 1u) << 3);
}

// =====================================================================
// Kernel 1: split-K fp16 2-term mma.sync GEMM, 2 CTAs/SM.
// R11 warp grid (warp w: b[0..64) x n[w*32,+32)), R11 B layout (528 pitch),
// A side XOR-swizzled conflict-free (64 B pitch).
// Prefetch distance 1: LDG(t+1) -> MMA(t) -> cvt+STS(t+1) -> sync.
// =====================================================================
__global__ void __launch_bounds__(256, 2)
sim_mma_kernel(const float* __restrict__ content, const float* __restrict__ bank) {
    extern __shared__ char smem[];
    const uint32_t sbase = smem_u32(smem);
    const int tid  = threadIdx.x;
    const int lane = tid & 31;
    const int w    = tid >> 5;
    const int bid  = blockIdx.x;

    const int tbase = NTT / NCTA2;                // 53
    const int trem  = NTT % NCTA2;                // 272
    const int t0 = bid * tbase + (bid < trem ? bid : trem);
    const int nt = tbase + (bid < trem ? 1 : 0);

    const int n4 = tid & 63;      // bank float4 column
    const int kq = tid >> 6;      // 0..3
    const int lr = lane & 15;
    const int lc = lane >> 4;

    // B STS offsets (R11 layout)
    const uint32_t bsts = (uint32_t)kq * 528u + (uint32_t)n4 * 8u;
    // A STS offsets (swizzled)
    const uint32_t asts0 = a_sts(tid);
    const uint32_t asts1 = a_sts(256 + tid);
    const int ct_b0 = tid >> 3, ct_k4 = tid & 7;
    const int ct_b1 = (256 + tid) >> 3;

    // A ldsm offsets (swizzled, conflict-free): row = fm*16+lr
    uint32_t aoff[2][4];
    #pragma unroll
    for (int kk = 0; kk < 2; ++kk)
        #pragma unroll
        for (int fm = 0; fm < 4; ++fm)
            aoff[kk][fm] = (uint32_t)(fm * 16 + lr) * 64u +
                ((((uint32_t)(kk * 2 + lc)) ^ (((uint32_t)lr >> 1) & 3u)) << 4);
    // B ldsm offsets (R11)
    uint32_t boff[2][2];
    #pragma unroll
    for (int kk = 0; kk < 2; ++kk)
        #pragma unroll
        for (int g = 0; g < 2; ++g)
            boff[kk][g] = (uint32_t)(kk * 16 + lr) * 528u +
                          (uint32_t)(w * 32 + g * 16 + lc * 8) * 2u;

    float acc[4][4][4];
    #pragma unroll
    for (int i = 0; i < 4; ++i)
        #pragma unroll
        for (int j = 0; j < 4; ++j)
            #pragma unroll
            for (int k = 0; k < 4; ++k) acc[i][j][k] = 0.f;
    float4 nrm = make_float4(0.f, 0.f, 0.f, 0.f);

    float4 bkreg[8];
    float4 ctreg[2];

    // ---- prologue: LDG(0), cvt+STS(0) -> buf0 ----
    {
        const long long d0 = (long long)t0 * KT;
        const float4* bs = (const float4*)bank + d0 * 64;
        #pragma unroll
        for (int i = 0; i < 8; ++i) bkreg[i] = bs[(i * 4 + kq) * 64 + n4];
        ctreg[0] = *(const float4*)(content + (long long)ct_b0 * DLL + d0 + ct_k4 * 4);
        ctreg[1] = *(const float4*)(content + (long long)ct_b1 * DLL + d0 + ct_k4 * 4);

        char* buf = smem;
        #pragma unroll
        for (int i = 0; i < 8; ++i) {
            *(uint2*)(buf + B_HI + bsts + (uint32_t)i * (4u * 528u)) = cvt4s(bkreg[i]);
            nrm.x = fmaf(bkreg[i].x, bkreg[i].x, nrm.x);
            nrm.y = fmaf(bkreg[i].y, bkreg[i].y, nrm.y);
            nrm.z = fmaf(bkreg[i].z, bkreg[i].z, nrm.z);
            nrm.w = fmaf(bkreg[i].w, bkreg[i].w, nrm.w);
        }
        uint2 hi, lo;
        cvt4h(ctreg[0], hi, lo);
        *(uint2*)(buf + A_HI + asts0) = hi;
        *(uint2*)(buf + A_LO + asts0) = lo;
        cvt4h(ctreg[1], hi, lo);
        *(uint2*)(buf + A_HI + asts1) = hi;
        *(uint2*)(buf + A_LO + asts1) = lo;
    }
    __syncthreads();

    for (int t = 0; t < nt; ++t) {
        const int p = t & 1;
        const bool more = (t + 1 < nt);

        // 1) LDG(t+1)
        if (more) {
            const long long d0n = (long long)(t0 + t + 1) * KT;
            const float4* bs = (const float4*)bank + d0n * 64;
            #pragma unroll
            for (int i = 0; i < 8; ++i) bkreg[i] = bs[(i * 4 + kq) * 64 + n4];
            ctreg[0] = *(const float4*)(content + (long long)ct_b0 * DLL + d0n + ct_k4 * 4);
            ctreg[1] = *(const float4*)(content + (long long)ct_b1 * DLL + d0n + ct_k4 * 4);
        }

        // 2) MMA(t) on buf p: 2 terms (Ah*Bh, Al*Bh)
        {
            const uint32_t bb = sbase + (uint32_t)p * BUFB;
            #pragma unroll
            for (int kk = 0; kk < 2; ++kk) {
                uint32_t ah[4][4], al[4][4];
                #pragma unroll
                for (int fm = 0; fm < 4; ++fm) {
                    ldsm4(ah[fm], bb + A_HI + aoff[kk][fm]);
                    ldsm4(al[fm], bb + A_LO + aoff[kk][fm]);
                }
                uint32_t bh[4][2];
                #pragma unroll
                for (int g = 0; g < 2; ++g) {
                    uint32_t r[4];
                    ldsm4t(r, bb + B_HI + boff[kk][g]);
                    bh[g * 2][0] = r[0]; bh[g * 2][1] = r[1];
                    bh[g * 2 + 1][0] = r[2]; bh[g * 2 + 1][1] = r[3];
                }
                #pragma unroll
                for (int fm = 0; fm < 4; ++fm)
                    #pragma unroll
                    for (int fn = 0; fn < 4; ++fn) {
                        mma16816(acc[fm][fn], ah[fm], bh[fn]);   // hi*hi
                        mma16816(acc[fm][fn], al[fm], bh[fn]);   // lo*hi
                    }
            }
        }

        // 3) cvt+STS(t+1) into the other buffer
        if (more) {
            char* buf = smem + (uint32_t)(p ^ 1) * BUFB;
            #pragma unroll
            for (int i = 0; i < 8; ++i) {
                *(uint2*)(buf + B_HI + bsts + (uint32_t)i * (4u * 528u)) = cvt4s(bkreg[i]);
                nrm.x = fmaf(bkreg[i].x, bkreg[i].x, nrm.x);
                nrm.y = fmaf(bkreg[i].y, bkreg[i].y, nrm.y);
                nrm.z = fmaf(bkreg[i].z, bkreg[i].z, nrm.z);
                nrm.w = fmaf(bkreg[i].w, bkreg[i].w, nrm.w);
            }
            uint2 hi, lo;
            cvt4h(ctreg[0], hi, lo);
            *(uint2*)(buf + A_HI + asts0) = hi;
            *(uint2*)(buf + A_LO + asts0) = lo;
            cvt4h(ctreg[1], hi, lo);
            *(uint2*)(buf + A_HI + asts1) = hi;
            *(uint2*)(buf + A_LO + asts1) = lo;
        }

        __syncthreads();
    }

    // ---- norm^2 reduce across the 4 k-quarters ----
    ((float4*)smem)[tid] = nrm;
    __syncthreads();
    if (tid < 64) {
        const float4* n = (const float4*)smem;
        float4 s0 = n[tid], s1 = n[tid + 64], s2 = n[tid + 128], s3 = n[tid + 192];
        float4 s = make_float4(s0.x + s1.x + s2.x + s3.x,
                               s0.y + s1.y + s2.y + s3.y,
                               s0.z + s1.z + s2.z + s3.z,
                               s0.w + s1.w + s2.w + s3.w);
        *(float4*)(g_pnorm + (size_t)bid * MB + tid * 4) = s;
    }

    // ---- psim write ----
    {
        float* ps = g_psim + (size_t)bid * (BQ * MB);
        const int gr = lane >> 2, c2 = (lane & 3) * 2;
        #pragma unroll
        for (int fm = 0; fm < 4; ++fm)
            #pragma unroll
            for (int fn = 0; fn < 4; ++fn) {
                const int b0 = fm * 16 + gr;
                const int n  = w * 32 + fn * 8 + c2;
                *(float2*)&ps[b0 * MB + n] =
                    make_float2(acc[fm][fn][0], acc[fm][fn][1]);
                *(float2*)&ps[(b0 + 8) * MB + n] =
                    make_float2(acc[fm][fn][2], acc[fm][fn][3]);
            }
    }
}

// =====================================================================
// Kernel 2a: pre-reduce chunk groups.  grid (64, NGRP), 256 threads.
// =====================================================================
__global__ __launch_bounds__(256)
void reduce_part_kernel() {
    const int b = blockIdx.x, g = blockIdx.y, m = threadIdx.x;
    const int c0 = g * CPG;
    float s = 0.f;
    #pragma unroll 4
    for (int c = c0; c < c0 + CPG; ++c)
        s += g_psim[(size_t)c * (BQ * MB) + b * MB + m];
    g_part[(b * NGRP + g) * MB + m] = s;
    if (b == 0) {
        float n = 0.f;
        #pragma unroll 4
        for (int c = c0; c < c0 + CPG; ++c)
            n += g_pnorm[(size_t)c * MB + m];
        g_npart[g * MB + m] = n;
    }
}

// =====================================================================
// Kernel 2b: final reduce -> score -> argmax -> gather. grid 64, 256 thr.
// =====================================================================
__global__ __launch_bounds__(256)
void argmax_gather_kernel(const float* __restrict__ style,
                          float* __restrict__ out) {
    const int b = blockIdx.x, tid = threadIdx.x;

    float s = 0.f, n2 = 0.f;
    #pragma unroll
    for (int g = 0; g < NGRP; ++g) {
        s  += g_part[(b * NGRP + g) * MB + tid];
        n2 += g_npart[g * MB + tid];
    }

    __shared__ float s_val[256];
    __shared__ int   s_idx[256];
    s_val[tid] = s / fmaxf(sqrtf(n2), 1e-12f);
    s_idx[tid] = tid;
    __syncthreads();

    #pragma unroll
    for (int st = 128; st > 0; st >>= 1) {
        if (tid < st) {
            const float v1 = s_val[tid + st], v0 = s_val[tid];
            const int   i1 = s_idx[tid + st], i0 = s_idx[tid];
            if (v1 > v0 || (v1 == v0 && i1 < i0)) {
                s_val[tid] = v1;
                s_idx[tid] = i1;
            }
        }
        __syncthreads();
    }
    const int idx = s_idx[0];

    const float4* src = (const float4*)(style + (size_t)idx * SDIM);
    float4* dst = (float4*)(out + (size_t)b * SDIM);
    dst[tid]       = src[tid];
    dst[tid + 256] = src[tid + 256];
}

extern "C" void kernel_launch(void* const* d_in, const int* in_sizes, int n_in,
                              void* d_out, int out_size) {
    const float* content = (const float*)d_in[0];
    const float* bank    = (const float*)d_in[1];
    const float* style   = (const float*)d_in[2];
    float* out = (float*)d_out;

    cudaFuncSetAttribute(sim_mma_kernel,
                         cudaFuncAttributeMaxDynamicSharedMemorySize, SMEM_TOTAL);

    sim_mma_kernel<<<NCTA2, 256, SMEM_TOTAL>>>(content, bank);
    reduce_part_kernel<<<dim3(BQ, NGRP), 256>>>();
    argmax_gather_kernel<<<BQ, 256>>>(style, out);
}

// round 15
// speedup vs baseline: 1.1611x; 1.1611x over previous
#include <cuda_runtime.h>
#include <cuda_fp16.h>
#include <cstdint>

// ---------------- problem constants ----------------
#define BQ 64            // batch (GEMM M)
#define MB 256           // bank entries (GEMM N)
#define DLL 524288LL     // feature dim K
#define KT 32            // K per tile
#define NTT 16384        // DLL / KT
#define NCTA2 304        // 2 CTAs per SM
#define SDIM 2048        // style dim
#define NGRP 16          // reduction groups
#define CPG  (NCTA2 / NGRP)   // 19 chunks per group

// static scratch
__device__ float g_psim[NCTA2 * BQ * MB];     // [chunk][b][m]
__device__ float g_pnorm[NCTA2 * MB];         // [chunk][m]
__device__ float g_part[BQ * NGRP * MB];      // [b][g][m]
__device__ float g_npart[NGRP * MB];          // [g][m]

// ---------------- smem layout (bytes, per buffer) -- R11 verbatim ----
// A (content): [64 b][k pitch 40] fp16 -> 5120 B (hi, lo)
// B (bank)   : [32 k][n pitch 264] fp16 -> 16896 B (hi only)
#define A_HI 0u
#define A_LO 5120u
#define B_HI 10240u
#define BUFB 27648u
#define SMEM_TOTAL (2u * BUFB)   // 55296 per CTA; x2 CTAs = 110.6 KB/SM

// ---------------- helpers ----------------
static __device__ __forceinline__ uint32_t smem_u32(const void* p) {
    uint32_t a;
    asm("{ .reg .u64 t; cvta.to.shared.u64 t, %1; cvt.u32.u64 %0, t; }"
        : "=r"(a) : "l"(p));
    return a;
}
static __device__ __forceinline__ void ldsm4(uint32_t* r, uint32_t addr) {
    asm volatile("ldmatrix.sync.aligned.m8n8.x4.shared.b16 {%0,%1,%2,%3}, [%4];"
                 : "=r"(r[0]), "=r"(r[1]), "=r"(r[2]), "=r"(r[3]) : "r"(addr));
}
static __device__ __forceinline__ void ldsm4t(uint32_t* r, uint32_t addr) {
    asm volatile("ldmatrix.sync.aligned.m8n8.x4.trans.shared.b16 {%0,%1,%2,%3}, [%4];"
                 : "=r"(r[0]), "=r"(r[1]), "=r"(r[2]), "=r"(r[3]) : "r"(addr));
}
static __device__ __forceinline__ void mma16816(float* c, const uint32_t* a,
                                                const uint32_t* b) {
    asm volatile(
        "mma.sync.aligned.m16n8k16.row.col.f32.f16.f16.f32 "
        "{%0,%1,%2,%3}, {%4,%5,%6,%7}, {%8,%9}, {%0,%1,%2,%3};"
        : "+f"(c[0]), "+f"(c[1]), "+f"(c[2]), "+f"(c[3])
        : "r"(a[0]), "r"(a[1]), "r"(a[2]), "r"(a[3]), "r"(b[0]), "r"(b[1]));
}
// fp32x4 -> fp16 hi/lo pairs (A side)
static __device__ __forceinline__ void cvt4h(float4 v, uint2& hi, uint2& lo) {
    __half2 h0 = __floats2half2_rn(v.x, v.y);
    __half2 h1 = __floats2half2_rn(v.z, v.w);
    float2 f0 = __half22float2(h0);
    float2 f1 = __half22float2(h1);
    __half2 l0 = __floats2half2_rn(v.x - f0.x, v.y - f0.y);
    __half2 l1 = __floats2half2_rn(v.z - f1.x, v.w - f1.y);
    hi = make_uint2(*(uint32_t*)&h0, *(uint32_t*)&h1);
    lo = make_uint2(*(uint32_t*)&l0, *(uint32_t*)&l1);
}
// fp32x4 -> fp16x4 (B side, single term)
static __device__ __forceinline__ uint2 cvt4s(float4 v) {
    __half2 h0 = __floats2half2_rn(v.x, v.y);
    __half2 h1 = __floats2half2_rn(v.z, v.w);
    return make_uint2(*(uint32_t*)&h0, *(uint32_t*)&h1);
}

// =====================================================================
// Kernel 1: split-K fp16 2-term mma.sync GEMM, 2 CTAs per SM.
// EXACT R11 configuration (best measured GEMM: 134.3 us).
// grid = 304, 256 threads. Warp w owns b[0..64) x n[w*32,+32).
// Prefetch distance 1: LDG(t+1) -> MMA(t) -> cvt+STS(t+1) -> sync.
// =====================================================================
__global__ void __launch_bounds__(256, 2)
sim_mma_kernel(const float* __restrict__ content, const float* __restrict__ bank) {
    extern __shared__ char smem[];
    const uint32_t sbase = smem_u32(smem);
    const int tid  = threadIdx.x;
    const int lane = tid & 31;
    const int w    = tid >> 5;
    const int bid  = blockIdx.x;

    const int tbase = NTT / NCTA2;                // 53
    const int trem  = NTT % NCTA2;                // 272
    const int t0 = bid * tbase + (bid < trem ? bid : trem);
    const int nt = tbase + (bid < trem ? 1 : 0);

    const int n4 = tid & 63;      // bank float4 column
    const int kq = tid >> 6;      // 0..3
    const int lr = lane & 15;
    const int lc = lane >> 4;

    const uint32_t bsts = (uint32_t)kq * 528u + (uint32_t)n4 * 8u;
    const int ct_b0 = tid >> 3, ct_k4 = tid & 7;
    const int ct_b1 = (256 + tid) >> 3;
    const uint32_t asts0 = (uint32_t)ct_b0 * 80u + (uint32_t)ct_k4 * 8u;
    const uint32_t asts1 = (uint32_t)ct_b1 * 80u + (uint32_t)ct_k4 * 8u;

    float acc[4][4][4];
    #pragma unroll
    for (int i = 0; i < 4; ++i)
        #pragma unroll
        for (int j = 0; j < 4; ++j)
            #pragma unroll
            for (int k = 0; k < 4; ++k) acc[i][j][k] = 0.f;
    float4 nrm = make_float4(0.f, 0.f, 0.f, 0.f);

    float4 bkreg[8];
    float4 ctreg[2];

    // ---- prologue: LDG(0), cvt+STS(0) -> buf0 ----
    {
        const long long d0 = (long long)t0 * KT;
        const float4* bs = (const float4*)bank + d0 * 64;
        #pragma unroll
        for (int i = 0; i < 8; ++i) bkreg[i] = bs[(i * 4 + kq) * 64 + n4];
        ctreg[0] = *(const float4*)(content + (long long)ct_b0 * DLL + d0 + ct_k4 * 4);
        ctreg[1] = *(const float4*)(content + (long long)ct_b1 * DLL + d0 + ct_k4 * 4);

        char* buf = smem;
        #pragma unroll
        for (int i = 0; i < 8; ++i) {
            *(uint2*)(buf + B_HI + bsts + (uint32_t)i * (4u * 528u)) = cvt4s(bkreg[i]);
            nrm.x = fmaf(bkreg[i].x, bkreg[i].x, nrm.x);
            nrm.y = fmaf(bkreg[i].y, bkreg[i].y, nrm.y);
            nrm.z = fmaf(bkreg[i].z, bkreg[i].z, nrm.z);
            nrm.w = fmaf(bkreg[i].w, bkreg[i].w, nrm.w);
        }
        uint2 hi, lo;
        cvt4h(ctreg[0], hi, lo);
        *(uint2*)(buf + A_HI + asts0) = hi;
        *(uint2*)(buf + A_LO + asts0) = lo;
        cvt4h(ctreg[1], hi, lo);
        *(uint2*)(buf + A_HI + asts1) = hi;
        *(uint2*)(buf + A_LO + asts1) = lo;
    }
    __syncthreads();

    for (int t = 0; t < nt; ++t) {
        const int p = t & 1;
        const bool more = (t + 1 < nt);

        // 1) LDG(t+1)
        if (more) {
            const long long d0n = (long long)(t0 + t + 1) * KT;
            const float4* bs = (const float4*)bank + d0n * 64;
            #pragma unroll
            for (int i = 0; i < 8; ++i) bkreg[i] = bs[(i * 4 + kq) * 64 + n4];
            ctreg[0] = *(const float4*)(content + (long long)ct_b0 * DLL + d0n + ct_k4 * 4);
            ctreg[1] = *(const float4*)(content + (long long)ct_b1 * DLL + d0n + ct_k4 * 4);
        }

        // 2) MMA(t) on buf p: 2 terms (Ah*Bh, Al*Bh)
        {
            const uint32_t bb = sbase + (uint32_t)p * BUFB;
            #pragma unroll
            for (int kk = 0; kk < 2; ++kk) {
                uint32_t ah[4][4], al[4][4];
                #pragma unroll
                for (int fm = 0; fm < 4; ++fm) {
                    const uint32_t aoff = (uint32_t)(fm * 16 + lr) * 80u +
                                          (uint32_t)(kk * 16 + lc * 8) * 2u;
                    ldsm4(ah[fm], bb + A_HI + aoff);
                    ldsm4(al[fm], bb + A_LO + aoff);
                }
                uint32_t bh[4][2];
                #pragma unroll
                for (int g = 0; g < 2; ++g) {
                    const uint32_t boff = (uint32_t)(kk * 16 + lr) * 528u +
                                          (uint32_t)(w * 32 + g * 16 + lc * 8) * 2u;
                    uint32_t r[4];
                    ldsm4t(r, bb + B_HI + boff);
                    bh[g * 2][0] = r[0]; bh[g * 2][1] = r[1];
                    bh[g * 2 + 1][0] = r[2]; bh[g * 2 + 1][1] = r[3];
                }
                #pragma unroll
                for (int fm = 0; fm < 4; ++fm)
                    #pragma unroll
                    for (int fn = 0; fn < 4; ++fn) {
                        mma16816(acc[fm][fn], ah[fm], bh[fn]);   // hi*hi
                        mma16816(acc[fm][fn], al[fm], bh[fn]);   // lo*hi
                    }
            }
        }

        // 3) cvt+STS(t+1) into the other buffer
        if (more) {
            char* buf = smem + (uint32_t)(p ^ 1) * BUFB;
            #pragma unroll
            for (int i = 0; i < 8; ++i) {
                *(uint2*)(buf + B_HI + bsts + (uint32_t)i * (4u * 528u)) = cvt4s(bkreg[i]);
                nrm.x = fmaf(bkreg[i].x, bkreg[i].x, nrm.x);
                nrm.y = fmaf(bkreg[i].y, bkreg[i].y, nrm.y);
                nrm.z = fmaf(bkreg[i].z, bkreg[i].z, nrm.z);
                nrm.w = fmaf(bkreg[i].w, bkreg[i].w, nrm.w);
            }
            uint2 hi, lo;
            cvt4h(ctreg[0], hi, lo);
            *(uint2*)(buf + A_HI + asts0) = hi;
            *(uint2*)(buf + A_LO + asts0) = lo;
            cvt4h(ctreg[1], hi, lo);
            *(uint2*)(buf + A_HI + asts1) = hi;
            *(uint2*)(buf + A_LO + asts1) = lo;
        }

        __syncthreads();
    }

    // ---- norm^2 reduce across the 4 k-quarters ----
    ((float4*)smem)[tid] = nrm;
    __syncthreads();
    if (tid < 64) {
        const float4* n = (const float4*)smem;
        float4 s0 = n[tid], s1 = n[tid + 64], s2 = n[tid + 128], s3 = n[tid + 192];
        float4 s = make_float4(s0.x + s1.x + s2.x + s3.x,
                               s0.y + s1.y + s2.y + s3.y,
                               s0.z + s1.z + s2.z + s3.z,
                               s0.w + s1.w + s2.w + s3.w);
        *(float4*)(g_pnorm + (size_t)bid * MB + tid * 4) = s;
    }

    // ---- psim write ----
    {
        float* ps = g_psim + (size_t)bid * (BQ * MB);
        const int gr = lane >> 2, c2 = (lane & 3) * 2;
        #pragma unroll
        for (int fm = 0; fm < 4; ++fm)
            #pragma unroll
            for (int fn = 0; fn < 4; ++fn) {
                const int b0 = fm * 16 + gr;
                const int n  = w * 32 + fn * 8 + c2;
                *(float2*)&ps[b0 * MB + n] =
                    make_float2(acc[fm][fn][0], acc[fm][fn][1]);
                *(float2*)&ps[(b0 + 8) * MB + n] =
                    make_float2(acc[fm][fn][2], acc[fm][fn][3]);
            }
    }
}

// =====================================================================
// Kernel 2a: pre-reduce chunk groups.  grid (64, NGRP), 256 threads.
// (R13 epilogue, measured ~6.4 us total for 2a+2b)
// =====================================================================
__global__ __launch_bounds__(256)
void reduce_part_kernel() {
    const int b = blockIdx.x, g = blockIdx.y, m = threadIdx.x;
    const int c0 = g * CPG;
    float s = 0.f;
    #pragma unroll 4
    for (int c = c0; c < c0 + CPG; ++c)
        s += g_psim[(size_t)c * (BQ * MB) + b * MB + m];
    g_part[(b * NGRP + g) * MB + m] = s;
    if (b == 0) {
        float n = 0.f;
        #pragma unroll 4
        for (int c = c0; c < c0 + CPG; ++c)
            n += g_pnorm[(size_t)c * MB + m];
        g_npart[g * MB + m] = n;
    }
}

// =====================================================================
// Kernel 2b: final reduce -> score -> argmax -> gather. grid 64, 256 thr.
// =====================================================================
__global__ __launch_bounds__(256)
void argmax_gather_kernel(const float* __restrict__ style,
                          float* __restrict__ out) {
    const int b = blockIdx.x, tid = threadIdx.x;

    float s = 0.f, n2 = 0.f;
    #pragma unroll
    for (int g = 0; g < NGRP; ++g) {
        s  += g_part[(b * NGRP + g) * MB + tid];
        n2 += g_npart[g * MB + tid];
    }

    __shared__ float s_val[256];
    __shared__ int   s_idx[256];
    s_val[tid] = s / fmaxf(sqrtf(n2), 1e-12f);
    s_idx[tid] = tid;
    __syncthreads();

    #pragma unroll
    for (int st = 128; st > 0; st >>= 1) {
        if (tid < st) {
            const float v1 = s_val[tid + st], v0 = s_val[tid];
            const int   i1 = s_idx[tid + st], i0 = s_idx[tid];
            if (v1 > v0 || (v1 == v0 && i1 < i0)) {
                s_val[tid] = v1;
                s_idx[tid] = i1;
            }
        }
        __syncthreads();
    }
    const int idx = s_idx[0];

    const float4* src = (const float4*)(style + (size_t)idx * SDIM);
    float4* dst = (float4*)(out + (size_t)b * SDIM);
    dst[tid]       = src[tid];
    dst[tid + 256] = src[tid + 256];
}

extern "C" void kernel_launch(void* const* d_in, const int* in_sizes, int n_in,
                              void* d_out, int out_size) {
    const float* content = (const float*)d_in[0];
    const float* bank    = (const float*)d_in[1];
    const float* style   = (const float*)d_in[2];
    float* out = (float*)d_out;

    cudaFuncSetAttribute(sim_mma_kernel,
                         cudaFuncAttributeMaxDynamicSharedMemorySize, SMEM_TOTAL);

    sim_mma_kernel<<<NCTA2, 256, SMEM_TOTAL>>>(content, bank);
    reduce_part_kernel<<<dim3(BQ, NGRP), 256>>>();
    argmax_gather_kernel<<<BQ, 256>>>(style, out);
}